// round 2
// baseline (speedup 1.0000x reference)
#include <cuda_runtime.h>

// SofaNetEllipse: batched (1024) tiny MLP 1->64->64->2 with JVP, trig epilogue,
// and mirrored extension 1025 -> 2049 columns.
//
// Inputs (metadata order): alpha[2049], w0[1024*64], w1[1024*64*64],
//   w2[1024*2*64], b0[1024*64], b1[1024*64], b2[1024*2]   (all float32)
// Output: float32, 4 arrays of shape (1024, 2049) concatenated:
//   xp, yp, xpp, ypp.

#define NAB   1024
#define NCOL  2049
#define HALF  1025
#define H     64
#define TPB   128

__device__ __forceinline__ float fast_tanh(float x) {
    // tanh(x) = 1 - 2/(exp(2x)+1); abs err ~1e-6, saturates correctly.
    float e = __expf(x + x);
    return 1.0f - __fdividef(2.0f, e + 1.0f);
}

__global__ __launch_bounds__(TPB)
void sofanet_kernel(const float* __restrict__ alpha,
                    const float* __restrict__ w0,
                    const float* __restrict__ w1,
                    const float* __restrict__ w2,
                    const float* __restrict__ b0,
                    const float* __restrict__ b1,
                    const float* __restrict__ b2,
                    float* __restrict__ out)
{
    const int n   = blockIdx.x;   // network id
    const int tid = threadIdx.x;

    __shared__ float w1s[H * H];          // 16 KB
    __shared__ float w0s[H], b0s[H], b1s[H];
    __shared__ float w2s[2 * H];
    __shared__ float b2s[2];
    __shared__ float xlast_s;

    // ---- stage weights for this network ----
    {
        const float4* src = reinterpret_cast<const float4*>(w1 + (size_t)n * H * H);
        float4* dst = reinterpret_cast<float4*>(w1s);
        #pragma unroll
        for (int i = tid; i < (H * H) / 4; i += TPB) dst[i] = src[i];

        if (tid < H) {
            w0s[tid] = w0[(size_t)n * H + tid];
            b0s[tid] = b0[(size_t)n * H + tid];
            b1s[tid] = b1[(size_t)n * H + tid];
        }
        if (tid < 2 * H) w2s[tid] = w2[(size_t)n * 2 * H + tid];
        if (tid < 2)     b2s[tid] = b2[(size_t)n * 2 + tid];
    }
    __syncthreads();

    const size_t AR  = (size_t)NAB * NCOL;      // stride between the 4 output arrays
    const size_t row = (size_t)n * NCOL;
    float xlast = 0.0f;

    // 9 strided iterations cover m = 0..1024; remap so m=0 -> t=1024 (needed
    // for the mirror constant 2*xp[:, -1]), computed in iteration k=0 by tid 0.
    for (int k = 0; k < 9; ++k) {
        const int m = k * TPB + tid;
        const bool active = (m < HALF);
        int t = 0;
        if (active) { t = m + (HALF - 1); if (t >= HALF) t -= HALF; }  // bijection

        float xp = 0.f, yp = 0.f, xpp = 0.f, ypp = 0.f;

        if (active) {
            const float x = alpha[t];

            // ---- layer 0: h1 = tanh(w0*x + b0); dh1 = (1-h1^2)*w0 ----
            float h1[H], d1[H];
            #pragma unroll
            for (int j = 0; j < H; ++j) {
                const float w  = w0s[j];
                const float th = fast_tanh(fmaf(w, x, b0s[j]));
                h1[j] = th;
                d1[j] = (1.0f - th * th) * w;
            }

            // ---- layer 1 fused with layer 2 accumulation ----
            float p0 = b2s[0], p1 = b2s[1];   // layer-2 value accumulators
            float q0 = 0.f,    q1 = 0.f;      // layer-2 tangent accumulators

            #pragma unroll 2
            for (int i = 0; i < H; i += 2) {
                float u0 = b1s[i], u1 = b1s[i + 1];
                float v0 = 0.f,    v1 = 0.f;
                const float* ra = &w1s[i * H];
                const float* rb = &w1s[i * H + H];
                #pragma unroll
                for (int j = 0; j < H; j += 4) {
                    const float4 wa = *reinterpret_cast<const float4*>(ra + j);
                    const float4 wb = *reinterpret_cast<const float4*>(rb + j);
                    u0 = fmaf(wa.x, h1[j    ], u0);
                    u0 = fmaf(wa.y, h1[j + 1], u0);
                    u0 = fmaf(wa.z, h1[j + 2], u0);
                    u0 = fmaf(wa.w, h1[j + 3], u0);
                    v0 = fmaf(wa.x, d1[j    ], v0);
                    v0 = fmaf(wa.y, d1[j + 1], v0);
                    v0 = fmaf(wa.z, d1[j + 2], v0);
                    v0 = fmaf(wa.w, d1[j + 3], v0);
                    u1 = fmaf(wb.x, h1[j    ], u1);
                    u1 = fmaf(wb.y, h1[j + 1], u1);
                    u1 = fmaf(wb.z, h1[j + 2], u1);
                    u1 = fmaf(wb.w, h1[j + 3], u1);
                    v1 = fmaf(wb.x, d1[j    ], v1);
                    v1 = fmaf(wb.y, d1[j + 1], v1);
                    v1 = fmaf(wb.z, d1[j + 2], v1);
                    v1 = fmaf(wb.w, d1[j + 3], v1);
                }
                const float ha  = fast_tanh(u0);
                const float hb  = fast_tanh(u1);
                const float dda = (1.0f - ha * ha) * v0;
                const float ddb = (1.0f - hb * hb) * v1;
                // layer 2: p = w2 @ h2 + b2 ; dp = w2 @ dh2
                p0 = fmaf(w2s[i    ], ha, p0);
                p1 = fmaf(w2s[H + i], ha, p1);
                q0 = fmaf(w2s[i    ], dda, q0);
                q1 = fmaf(w2s[H + i], dda, q1);
                p0 = fmaf(w2s[i + 1    ], hb, p0);
                p1 = fmaf(w2s[H + i + 1], hb, p1);
                q0 = fmaf(w2s[i + 1    ], ddb, q0);
                q1 = fmaf(w2s[H + i + 1], ddb, q1);
            }

            // ---- square + JVP of square ----
            const float a  = p0 * p0;
            const float b  = p1 * p1;
            const float da = 2.0f * p0 * q0;
            const float db = 2.0f * p1 * q1;

            // ---- trig epilogue (cos(x)-1 = -2*sin^2(x/2), cancellation-free) ----
            const float s2  = sinf(0.5f * x);
            const float cm1 = -2.0f * s2 * s2;      // cos(x) - 1
            const float sa  = sinf(x);
            const float ca  = 1.0f + cm1;           // cos(x)

            xp  = a * cm1;
            yp  = b * sa;
            xpp = fmaf(da, cm1, -a * sa);
            ypp = fmaf(db, sa,  b * ca);

            // primary writes (columns 0..1024)
            out[           row + t] = xp;
            out[AR       + row + t] = yp;
            out[2 * AR   + row + t] = xpp;
            out[3 * AR   + row + t] = ypp;

            if (t == HALF - 1) xlast_s = xp;   // only (k=0, tid=0)
        }

        if (k == 0) {            // uniform branch: all threads participate
            __syncthreads();
            xlast = xlast_s;
        }

        // mirror writes: dest col 2048 - t for t in 0..1023
        if (active && t < HALF - 1) {
            const int c2 = (NCOL - 1) - t;
            out[           row + c2] = 2.0f * xlast - xp;
            out[AR       + row + c2] = yp;
            out[2 * AR   + row + c2] = xpp;
            out[3 * AR   + row + c2] = -ypp;
        }
    }
}

extern "C" void kernel_launch(void* const* d_in, const int* in_sizes, int n_in,
                              void* d_out, int out_size)
{
    const float* alpha = (const float*)d_in[0];
    const float* w0    = (const float*)d_in[1];
    const float* w1    = (const float*)d_in[2];
    const float* w2    = (const float*)d_in[3];
    const float* b0    = (const float*)d_in[4];
    const float* b1    = (const float*)d_in[5];
    const float* b2    = (const float*)d_in[6];
    float* out = (float*)d_out;

    sofanet_kernel<<<NAB, TPB>>>(alpha, w0, w1, w2, b0, b1, b2, out);
}